// round 17
// baseline (speedup 1.0000x reference)
#include <cuda_runtime.h>

// Fixed problem shape
#define BB 256
#define TT 4096
#define CC 16
#define HH 20
#define GG 60
#define K  16
#define NC (TT / K)   // 256 chunks

typedef unsigned long long u64;

__device__ __forceinline__ u64 pack2(float a, float b) {
    u64 r; asm("mov.b64 %0,{%1,%2};" : "=l"(r) : "f"(a), "f"(b)); return r;
}
__device__ __forceinline__ void unpack2(u64 v, float& a, float& b) {
    asm("mov.b64 {%0,%1},%2;" : "=f"(a), "=f"(b) : "l"(v));
}
__device__ __forceinline__ void fma2(u64& d, u64 a, u64 b) {
    asm("fma.rn.f32x2 %0,%1,%2,%0;" : "+l"(d) : "l"(a), "l"(b));
}
__device__ __forceinline__ float hsum2(u64 v) {
    float x, y; unpack2(v, x, y); return x + y;
}
__device__ __forceinline__ float tanha(float x) {
    float y; asm("tanh.approx.f32 %0,%1;" : "=f"(y) : "f"(x)); return y;
}
__device__ __forceinline__ void batch_bar(int id) {
    asm volatile("bar.sync %0, 128;" :: "r"(id) : "memory");
}

#define LOAD_HP(ptr) do { \
    const ulonglong2* _h = (const ulonglong2*)(ptr); \
    ulonglong2 _p0=_h[0], _p1=_h[1], _p2=_h[2], _p3=_h[3], _p4=_h[4]; \
    hp[0]=_p0.x; hp[1]=_p0.y; hp[2]=_p1.x; hp[3]=_p1.y; hp[4]=_p2.x; \
    hp[5]=_p2.y; hp[6]=_p3.x; hp[7]=_p3.y; hp[8]=_p4.x; hp[9]=_p4.y; } while (0)

// ---------------------------------------------------------------------------
// IDLE-LANE ABSORPTION of GX1 into the chain warps.
// The chain's 30 fma2 per step have per-lane operands: lanes 0-19 run the
// recurrence (hp = broadcast h); lanes 20-31 carry W_ih1 rows in wh[] and the
// lagged h0 row in hp[], so the SAME instructions compute gx1 = W_ih1.h0.
// GX1 warp eliminated (its 80 pipe-cyc/step absorbed at zero pipe cost).
//   L0' idle lanes (12): gx1 rows 0..35 of chunk c-2
//   L1' idle lanes (8):  gx1 rows 36..59 of chunk c-2
// GX0 is split into two half-warps (steps 0-7 / 8-15) so each SMSP hosts
// exactly one chain warp + one light half-GX0.
//
// Warp map (SMSP = w%4; chain warps at HIGH wid):
//   w0=GX0a+head(A) S0   w1=GX0b+xDMA(A) S1   w2=GX0a+head(B) S2   w3=GX0b+xDMA(B) S3
//   w4=L0'(A)       S0   w5=L1'(A)       S1   w6=L0'(B)       S2   w7=L1'(B)      S3
// Lags: GX0 chunk c, L0 c-1, gx1(idle) c-2, L1 c-3, head c-4. Rings 2-deep.
// Edge iterations (chain inactive, gx1 active) run through the same loop with
// chain work predicated off (hp/h preserved).  Per-batch named barriers.
// sigmoid(s) = fma(tanh.approx(prescaled_sum), 0.5, 0.5); r/z rows prescaled.
// ---------------------------------------------------------------------------
__global__ void __launch_bounds__(256, 1)
fused_gru_kernel(const float* __restrict__ x,      // [B,T,C]
                 const float* __restrict__ h0in,   // [B,2,H]
                 const float* __restrict__ W_ih0, const float* __restrict__ W_hh0,
                 const float* __restrict__ b_ih0, const float* __restrict__ b_hh0,
                 const float* __restrict__ W_ih1, const float* __restrict__ W_hh1,
                 const float* __restrict__ b_ih1, const float* __restrict__ b_hh1,
                 const float* __restrict__ W_o,   const float* __restrict__ b_o,
                 float* __restrict__ out)          // o[B*T] then h_n[B,2,H]
{
    __shared__ __align__(16) float s_gx0[2][2][K][GG];  // 15 KB
    __shared__ __align__(16) float s_gx1[2][2][K][GG];  // 15 KB
    __shared__ __align__(16) float s_h0 [2][2][K][HH];  // 5 KB
    __shared__ __align__(16) float s_h1 [2][2][K][HH];  // 5 KB
    __shared__ __align__(16) float s_x  [2][2][K][CC];  // 4 KB

    const int tid = threadIdx.x;
    const int w   = tid >> 5;
    const int i   = tid & 31;
    const bool act = (i < HH);
    const unsigned FULL = 0xFFFFFFFFu;

    const bool low  = (w < 4);
    const int bs    = low ? (w >> 1) : ((w - 4) >> 1);
    const int kind  = w & 1;   // low: 0=GX0a+head 1=GX0b+DMA ; high: 0=L0' 1=L1'
    const int bar   = bs + 1;
    const int b     = blockIdx.x * 2 + bs;
    const float* xb = x + (size_t)b * TT * CC;

    // ---- prime x chunk 0 (GX0b warps): 256 floats = 64 float4 --------------
    if (low && kind == 1) {
        const float4* src = (const float4*)xb;
        float4* dst = (float4*)&s_x[bs][0][0][0];
        dst[i] = src[i]; dst[i + 32] = src[i + 32];
    }
    __syncthreads();

    if (low) {
        // ============ GX0 half-warp (scalar RN/Z) + head (a) / DMA (b) =======
        const bool zl = (i >= HH) && (i < 30);
        const bool gxon = (i < 30);
        int rowA = 0, rowB = 0; float scA = 0.f, scB = 0.f;
        if (act)     { rowA = i;                 scA = 0.5f; rowB = 2 * HH + i; scB = 1.0f; }
        else if (zl) { rowA = HH + 2 * (i - HH); scA = 0.5f; rowB = rowA + 1;   scB = 0.5f; }
        float wA[CC], wB[CC], bA = 0.f, bB = 0.f;
#pragma unroll
        for (int c2 = 0; c2 < CC; ++c2) {
            wA[c2] = scA * W_ih0[rowA * CC + c2];
            wB[c2] = scB * W_ih0[rowB * CC + c2];
        }
        bA = scA * b_ih0[rowA]; bB = scB * b_ih0[rowB];

        const int sBeg = (kind == 0) ? 0 : (K / 2);
        const int sEnd = sBeg + K / 2;
        u64 wo2[10]; float bo = 0.f;
        if (kind == 0) {
#pragma unroll
            for (int k = 0; k < 10; ++k)
                wo2[k] = pack2(W_o[2 * k], W_o[2 * k + 1]);
            bo = b_o[0];
        }
        float* ob = out + (size_t)b * TT;

        for (int c = 0; c < NC + 4; ++c) {
            float4 pf0, pf1;
            const bool pf = (kind == 1) && (c + 1 < NC);
            if (pf) {
                const float4* src = (const float4*)(xb + (size_t)(c + 1) * K * CC);
                pf0 = src[i]; pf1 = src[i + 32];
            }
            if (c < NC) {
                const float* xs = &s_x[bs][c & 1][0][0];
                float* go = &s_gx0[bs][c & 1][0][0];
#pragma unroll 4
                for (int s = sBeg; s < sEnd; ++s) {
                    const float4* x4 = (const float4*)(xs + s * CC);
                    float4 p0 = x4[0], p1 = x4[1], p2 = x4[2], p3 = x4[3];
                    float xf[CC] = {p0.x, p0.y, p0.z, p0.w, p1.x, p1.y, p1.z, p1.w,
                                    p2.x, p2.y, p2.z, p2.w, p3.x, p3.y, p3.z, p3.w};
                    float A0 = bA, A1 = 0.f, B0 = bB, B1 = 0.f;
#pragma unroll
                    for (int j = 0; j < CC; j += 2) {
                        A0 = fmaf(wA[j],     xf[j],     A0);
                        A1 = fmaf(wA[j + 1], xf[j + 1], A1);
                        B0 = fmaf(wB[j],     xf[j],     B0);
                        B1 = fmaf(wB[j + 1], xf[j + 1], B1);
                    }
                    if (gxon) {
                        go[s * GG + rowA] = A0 + A1;
                        go[s * GG + rowB] = B0 + B1;
                    }
                }
            }
            if (kind == 0) {
                // output head for chunk c-4: lane l<K handles step l
                const int ch = c - 4;
                if (ch >= 0 && i < K) {
                    const ulonglong2* hv2 = (const ulonglong2*)&s_h1[bs][ch & 1][i][0];
                    ulonglong2 p0 = hv2[0], p1 = hv2[1], p2 = hv2[2], p3 = hv2[3], p4 = hv2[4];
                    u64 hq[10] = {p0.x, p0.y, p1.x, p1.y, p2.x, p2.y, p3.x, p3.y, p4.x, p4.y};
                    u64 acc = pack2(bo, 0.f);
#pragma unroll
                    for (int k = 0; k < 10; ++k) fma2(acc, wo2[k], hq[k]);
                    ob[ch * K + i] = hsum2(acc);
                }
            }
            if (pf) {
                float4* dst = (float4*)&s_x[bs][(c + 1) & 1][0][0];
                dst[i] = pf0; dst[i + 32] = pf1;
            }
            batch_bar(bar);
        }
    } else {
        // ============ L0' / L1': chain + idle-lane gx1 =======================
        const bool isL0  = (kind == 0);
        const float* Whh = isL0 ? W_hh0 : W_hh1;
        const float* bhh = isL0 ? b_hh0 : b_hh1;
        const int lag    = isL0 ? 1 : 3;
        const int layer  = kind;

        // idle-lane gx1 row assignment
        const int p = i - HH;                         // 0..11 for idle lanes
        const bool hasRows = !act && (isL0 ? (p < 12) : (p < 8));
        const int base = isL0 ? 3 * p : (36 + 3 * p); // first of 3 rows

        u64 wh[30];
        float br = 0.f, bz = 0.f, bn = 0.f, h = 0.f;
        if (act) {
            // chain lanes: W_hh rows (r,z,n) for unit i; r/z prescaled 0.5
#pragma unroll
            for (int g = 0; g < 3; ++g) {
                const float sc = (g < 2) ? 0.5f : 1.0f;
#pragma unroll
                for (int k = 0; k < 10; ++k)
                    wh[g * 10 + k] = pack2(sc * Whh[(g * HH + i) * HH + 2 * k],
                                           sc * Whh[(g * HH + i) * HH + 2 * k + 1]);
            }
            br = 0.5f * bhh[i]; bz = 0.5f * bhh[HH + i]; bn = bhh[2 * HH + i];
            h = h0in[(b * 2 + layer) * HH + i];
        } else {
            // idle lanes: W_ih1 rows base..base+2 (prescale r/z rows by 0.5)
#pragma unroll
            for (int q = 0; q < 3; ++q) {
                const int row = base + q;
                const float rsc = (hasRows && row < 2 * HH) ? 0.5f : 1.0f;
#pragma unroll
                for (int k = 0; k < 10; ++k)
                    wh[q * 10 + k] = hasRows
                        ? pack2(rsc * W_ih1[row * HH + 2 * k],
                                rsc * W_ih1[row * HH + 2 * k + 1])
                        : pack2(0.f, 0.f);
                const float bv = hasRows ? rsc * b_ih1[row] : 0.f;
                if (q == 0) br = bv; else if (q == 1) bz = bv; else bn = bv;
            }
        }

        // initial broadcast of h (chain lanes; idle lanes overwritten below)
        u64 hp[10];
#pragma unroll
        for (int k = 0; k < 10; ++k)
            hp[k] = pack2(__shfl_sync(FULL, h, 2 * k),
                          __shfl_sync(FULL, h, 2 * k + 1));

        for (int c = 0; c < NC + 4; ++c) {
            const int cc = c - lag;          // chain chunk
            const int cg = c - 2;            // gx1 chunk (idle lanes)
            const bool ccOK = (cc >= 0) && (cc < NC);
            const bool cgOK = (cg >= 0) && (cg < NC);
            if (ccOK || cgOK) {
                const int ccc = ccOK ? cc : 0;
                const int cgc = cgOK ? cg : 0;
                const float* gxp = isL0 ? &s_gx0[bs][ccc & 1][0][0]
                                        : &s_gx1[bs][ccc & 1][0][0];
                float* hw  = isL0 ? &s_h0[bs][ccc & 1][0][0]
                                  : &s_h1[bs][ccc & 1][0][0];
                const float* hlag = &s_h0[bs][cgc & 1][0][0];
                float* g1o = &s_gx1[bs][cgc & 1][0][0];
                const bool gxw = cgOK && hasRows;

                // prologue: idle lanes load hp = h0_lag row 0
                if (!act) LOAD_HP(hlag);

#pragma unroll 2
                for (int s = 0; s < K; ++s) {
                    float gr = 0.f, gz = 0.f, gn = 0.f;
                    if (ccOK && act) {
                        gr = gxp[s * GG + i];
                        gz = gxp[s * GG + HH + i];
                        gn = gxp[s * GG + 2 * HH + i];
                    }
                    // shared fma2 stream: chain dots (lanes 0-19) AND gx1
                    // dots (lanes 20-31) in the SAME instructions.
                    u64 ar = pack2(br, gr);
#pragma unroll
                    for (int k = 0; k < 10; ++k) fma2(ar, wh[k], hp[k]);
                    u64 az = pack2(bz, gz);
#pragma unroll
                    for (int k = 0; k < 10; ++k) fma2(az, wh[10 + k], hp[k]);
                    u64 an = pack2(bn, 0.f);
#pragma unroll
                    for (int k = 0; k < 10; ++k) fma2(an, wh[20 + k], hp[k]);

                    // idle lanes: store 3 gx1 outputs (fills free issue slots)
                    if (gxw) {
                        g1o[s * GG + base]     = hsum2(ar);
                        g1o[s * GG + base + 1] = hsum2(az);
                        g1o[s * GG + base + 2] = hsum2(an);
                    }
                    // chain lanes: activations + state update
                    if (ccOK && act) {
                        const float r = fmaf(tanha(hsum2(ar)), 0.5f, 0.5f);
                        const float z = fmaf(tanha(hsum2(az)), 0.5f, 0.5f);
                        const float n = tanha(fmaf(r, hsum2(an), gn));
                        h = fmaf(z, h - n, n);
                        hw[s * HH + i] = h;
                    }
                    asm volatile("" ::: "memory");
                    // per-lane reload: chain lanes re-read the fresh h row;
                    // idle lanes read h0_lag[s+1] (clamped at chunk end)
                    const int s2 = (s + 1 < K) ? (s + 1) : (K - 1);
                    const float* rsrc = act ? (hw + s * HH) : (hlag + s2 * HH);
                    if (!act || ccOK) LOAD_HP(rsrc);
                }
            }
            batch_bar(bar);
        }
        if (act) out[(size_t)BB * TT + (b * 2 + layer) * HH + i] = h;
    }
}

// ---------------------------------------------------------------------------
extern "C" void kernel_launch(void* const* d_in, const int* in_sizes, int n_in,
                              void* d_out, int out_size) {
    const float* x     = (const float*)d_in[0];
    const float* h0    = (const float*)d_in[1];
    const float* W_ih0 = (const float*)d_in[2];
    const float* W_hh0 = (const float*)d_in[3];
    const float* b_ih0 = (const float*)d_in[4];
    const float* b_hh0 = (const float*)d_in[5];
    const float* W_ih1 = (const float*)d_in[6];
    const float* W_hh1 = (const float*)d_in[7];
    const float* b_ih1 = (const float*)d_in[8];
    const float* b_hh1 = (const float*)d_in[9];
    const float* W_o   = (const float*)d_in[10];
    const float* b_o   = (const float*)d_in[11];

    fused_gru_kernel<<<BB / 2, 256>>>(x, h0, W_ih0, W_hh0, b_ih0, b_hh0,
                                      W_ih1, W_hh1, b_ih1, b_hh1, W_o, b_o,
                                      (float*)d_out);
}